// round 10
// baseline (speedup 1.0000x reference)
#include <cuda_runtime.h>

// ---------------------------------------------------------------------------
// MPNN forward, fp32, graph-capturable, allocation-free.
// R10: edge MLP — channel-pair f32x2 everywhere, conflict-free swizzled
// dup staging (STS.128), win buffer reused for dup'd hidden, 20 warps/CTA.
// GRU = R5 f32x2 version.
// ---------------------------------------------------------------------------

#define N_NODES 50000
#define N_EDGES 800000
#define NODE_DIM 32
#define EDGE_DIM 16
#define HID 64
#define MSG_HID 128
#define NUM_GRAPHS 512
#define NUM_MP 3
#define S2S_STEPS 6
#define IN_DIM (2 * HID + EDGE_DIM)  // 144

// ------------------------- scratch (device globals) ------------------------
__device__ float g_x[N_NODES * HID];
__device__ float g_m[N_NODES * HID];
__device__ float g_qh[NUM_GRAPHS * HID];
__device__ float g_qc[NUM_GRAPHS * HID];
__device__ float g_qstar[NUM_GRAPHS * 2 * HID];
__device__ float g_e[N_NODES];
__device__ float g_a[N_NODES];
__device__ unsigned g_emax[NUM_GRAPHS];
__device__ float g_asum[NUM_GRAPHS];
__device__ float g_rvec[NUM_GRAPHS * HID];

__device__ __forceinline__ float sigmoidf_(float x) { return 1.f / (1.f + expf(-x)); }

__device__ __forceinline__ unsigned enc_f(float f) {
    unsigned u = __float_as_uint(f);
    return (u & 0x80000000u) ? ~u : (u | 0x80000000u);
}
__device__ __forceinline__ float dec_f(unsigned k) {
    return (k & 0x80000000u) ? __uint_as_float(k & 0x7fffffffu)
                             : __uint_as_float(~k);
}

// ----------------------- packed f32x2 helpers (sm_100+) --------------------
__device__ __forceinline__ unsigned long long fma2(unsigned long long a,
                                                   unsigned long long b,
                                                   unsigned long long c) {
    unsigned long long d;
    asm("fma.rn.f32x2 %0, %1, %2, %3;" : "=l"(d) : "l"(a), "l"(b), "l"(c));
    return d;
}
__device__ __forceinline__ float2 unpk(unsigned long long v) {
    float lo, hi;
    asm("mov.b64 {%0, %1}, %2;" : "=f"(lo), "=f"(hi) : "l"(v));
    return make_float2(lo, hi);
}
__device__ __forceinline__ unsigned long long ld2u(const float* p) {
    return *(const unsigned long long*)p;
}

// ------------------------------ zero kernels -------------------------------
__global__ void zero_m_kernel() {
    int t = blockIdx.x * blockDim.x + threadIdx.x;
    if (t < N_NODES * HID) g_m[t] = 0.f;
}
__global__ void zero_s2s_state_kernel() {
    int t = blockIdx.x * blockDim.x + threadIdx.x;
    if (t < NUM_GRAPHS * HID) { g_qh[t] = 0.f; g_qc[t] = 0.f; }
    if (t < NUM_GRAPHS * 2 * HID) g_qstar[t] = 0.f;
}
__global__ void zero_attn_kernel() {
    int t = blockIdx.x * blockDim.x + threadIdx.x;
    if (t < NUM_GRAPHS) { g_emax[t] = 0u; g_asum[t] = 0.f; }
    if (t < NUM_GRAPHS * HID) g_rvec[t] = 0.f;
}

// ------------------------------- embedding ---------------------------------
__global__ void embed_kernel(const float* __restrict__ xf,
                             const float* __restrict__ W,
                             const float* __restrict__ b) {
    int t = blockIdx.x * blockDim.x + threadIdx.x;
    if (t >= N_NODES * HID) return;
    int v = t >> 6, o = t & 63;
    const float* xr = xf + v * NODE_DIM;
    float acc = b[o];
#pragma unroll
    for (int c = 0; c < NODE_DIM; c++) acc += xr[c] * W[c * HID + o];
    g_x[t] = acc;
}

// ------------------------- edge message MLP kernel -------------------------
// 20 warps, EQ=4 edges/warp.
// Staging buffer (per warp, 1152 floats): channel idx occupies 8 floats (32B):
//   halfA (edges 0,1 dup'd) at idx*8 + 4*a, halfB (edges 2,3) at idx*8 + 4*(1-a)
//   where a = (idx>>2)&1 — 1-bit swizzle makes the STS.128 stores conflict-free.
// The SAME buffer is reused for the dup'd hidden activations (128 channels).
#define EK_THREADS 640
#define EK_WARPS 20
#define EQ 4
#define STG_F (IN_DIM * 8)   // 1152 floats per warp (hidden needs 1024 <= this)
#define EK_SMEM_FLOATS (IN_DIM * MSG_HID + MSG_HID + MSG_HID * HID + HID + \
                        EK_WARPS * STG_F)

__global__ __launch_bounds__(EK_THREADS, 1)
void edge_msg_kernel(const int* __restrict__ ei, const float* __restrict__ ea,
                     const float* __restrict__ W1, const float* __restrict__ b1,
                     const float* __restrict__ W2, const float* __restrict__ b2) {
    extern __shared__ float smem[];
    float* W1s  = smem;                              // 144*128 row-major
    float* b1s  = W1s + IN_DIM * MSG_HID;            // 128
    float* W2s  = b1s + MSG_HID;                     // 128*64 row-major
    float* b2s  = W2s + MSG_HID * HID;               // 64
    float* stg_all = b2s + HID;                      // warps * 1152

    int tid = threadIdx.x;
    for (int i = tid; i < IN_DIM * MSG_HID / 4; i += EK_THREADS)
        ((float4*)W1s)[i] = ((const float4*)W1)[i];
    for (int i = tid; i < MSG_HID; i += EK_THREADS) b1s[i] = b1[i];
    for (int i = tid; i < MSG_HID * HID / 4; i += EK_THREADS)
        ((float4*)W2s)[i] = ((const float4*)W2)[i];
    for (int i = tid; i < HID; i += EK_THREADS) b2s[i] = b2[i];
    __syncthreads();

    int warp = tid >> 5, lane = tid & 31;
    float* stg = stg_all + warp * STG_F;
    const int* src = ei;
    const int* dst = ei + N_EDGES;

    const int aL = (lane >> 2) & 1;   // staging swizzle bit (same for all j)
    const int aH = (lane >> 1) & 1;   // hidden-store swizzle bit (c = 2*lane..)

    const int nquads = N_EDGES / EQ;
    for (int q = blockIdx.x * EK_WARPS + warp; q < nquads;
         q += gridDim.x * EK_WARPS) {
        int e0 = q * EQ;
        int d[EQ];
        int s_[EQ];
#pragma unroll
        for (int k = 0; k < EQ; k++) {
            s_[k] = __ldg(src + e0 + k);
            d[k]  = __ldg(dst + e0 + k);
        }
        // gather: channel idx = lane + 32j; stage dup'd halves (swizzled)
#pragma unroll
        for (int j = 0; j < 5; j++) {
            int idx = lane + 32 * j;
            if (idx < IN_DIM) {
                float v[EQ];
#pragma unroll
                for (int k = 0; k < EQ; k++) {
                    float vv;
                    if (j < 2) vv = g_x[d[k] * HID + idx];
                    else if (j < 4) vv = g_x[s_[k] * HID + (idx - HID)];
                    else vv = __ldg(ea + (e0 + k) * EDGE_DIM + (idx - 2 * HID));
                    v[k] = vv;
                }
                float* base = stg + idx * 8;
                *(float4*)(base + 4 * aL) = make_float4(v[0], v[0], v[1], v[1]);
                *(float4*)(base + 4 * (1 - aL)) = make_float4(v[2], v[2], v[3], v[3]);
            }
        }
        __syncwarp();

        // ---- layer 1: lane owns channel pairs p0=lane, p1=lane+32 ----
        unsigned long long acc[2][EQ];
#pragma unroll
        for (int j = 0; j < 2; j++)
#pragma unroll
            for (int k = 0; k < EQ; k++) acc[j][k] = 0ull;

        for (int i0 = 0; i0 < IN_DIM; i0 += 8) {
#pragma unroll
            for (int t = 0; t < 8; t++) {
                int i = i0 + t;
                const int a = (t >> 2) & 1;  // == (i>>2)&1
                const float* base = stg + i * 8;
                unsigned long long in0 = ld2u(base + 4 * a);
                unsigned long long in1 = ld2u(base + 4 * a + 2);
                unsigned long long in2 = ld2u(base + 4 * (1 - a));
                unsigned long long in3 = ld2u(base + 4 * (1 - a) + 2);
                unsigned long long w0 = ld2u(W1s + i * MSG_HID + 2 * lane);
                unsigned long long w1 = ld2u(W1s + i * MSG_HID + 2 * lane + 64);
                acc[0][0] = fma2(w0, in0, acc[0][0]);
                acc[0][1] = fma2(w0, in1, acc[0][1]);
                acc[0][2] = fma2(w0, in2, acc[0][2]);
                acc[0][3] = fma2(w0, in3, acc[0][3]);
                acc[1][0] = fma2(w1, in0, acc[1][0]);
                acc[1][1] = fma2(w1, in1, acc[1][1]);
                acc[1][2] = fma2(w1, in2, acc[1][2]);
                acc[1][3] = fma2(w1, in3, acc[1][3]);
            }
        }
        __syncwarp();  // all lanes finished reading stg (layer-1 inputs)

        // bias + relu; write dup'd hidden into the SAME buffer (channels
        // c = 2p, 2p+1 for p = lane, lane+32), swizzled like the input.
#pragma unroll
        for (int j = 0; j < 2; j++) {
            int p = lane + 32 * j;
            float2 bp = ((const float2*)b1s)[p];
            float2 f0 = unpk(acc[j][0]);
            float2 f1 = unpk(acc[j][1]);
            float2 f2 = unpk(acc[j][2]);
            float2 f3 = unpk(acc[j][3]);
            float h0x = fmaxf(f0.x + bp.x, 0.f), h1x = fmaxf(f1.x + bp.x, 0.f);
            float h2x = fmaxf(f2.x + bp.x, 0.f), h3x = fmaxf(f3.x + bp.x, 0.f);
            float h0y = fmaxf(f0.y + bp.y, 0.f), h1y = fmaxf(f1.y + bp.y, 0.f);
            float h2y = fmaxf(f2.y + bp.y, 0.f), h3y = fmaxf(f3.y + bp.y, 0.f);
            float* baseX = stg + (2 * p) * 8;      // channel 2p
            float* baseY = stg + (2 * p + 1) * 8;  // channel 2p+1
            *(float4*)(baseX + 4 * aH) = make_float4(h0x, h0x, h1x, h1x);
            *(float4*)(baseX + 4 * (1 - aH)) = make_float4(h2x, h2x, h3x, h3x);
            *(float4*)(baseY + 4 * aH) = make_float4(h0y, h0y, h1y, h1y);
            *(float4*)(baseY + 4 * (1 - aH)) = make_float4(h2y, h2y, h3y, h3y);
        }
        __syncwarp();

        // ---- layer 2: lane owns channel pair lane -> channels 2l, 2l+1 ----
        unsigned long long acc2[EQ];
#pragma unroll
        for (int k = 0; k < EQ; k++) acc2[k] = 0ull;
        for (int i0 = 0; i0 < MSG_HID; i0 += 8) {
#pragma unroll
            for (int t = 0; t < 8; t++) {
                int i = i0 + t;
                const int a = (t >> 2) & 1;
                const float* base = stg + i * 8;
                unsigned long long in0 = ld2u(base + 4 * a);
                unsigned long long in1 = ld2u(base + 4 * a + 2);
                unsigned long long in2 = ld2u(base + 4 * (1 - a));
                unsigned long long in3 = ld2u(base + 4 * (1 - a) + 2);
                unsigned long long w = ld2u(W2s + i * HID + 2 * lane);
                acc2[0] = fma2(w, in0, acc2[0]);
                acc2[1] = fma2(w, in1, acc2[1]);
                acc2[2] = fma2(w, in2, acc2[2]);
                acc2[3] = fma2(w, in3, acc2[3]);
            }
        }
        float2 bp2 = ((const float2*)b2s)[lane];
#pragma unroll
        for (int k = 0; k < EQ; k++) {
            float2 f = unpk(acc2[k]);
            atomicAdd(&g_m[d[k] * HID + 2 * lane], f.x + bp2.x);
            atomicAdd(&g_m[d[k] * HID + 2 * lane + 1], f.y + bp2.y);
        }
        __syncwarp();  // done reading stg before next quad's staging
    }
}

// --------------------------------- GRU -------------------------------------
#define GK_THREADS 256
#define GK_WARPS 8
#define NPW 4
#define GRU_SMEM_F (64 * 96 * 2 * 2 + 384 + GK_WARPS * NPW * 128 * 2)

__global__ __launch_bounds__(GK_THREADS, 1)
void gru_kernel(const float* __restrict__ Wih, const float* __restrict__ Whh,
                const float* __restrict__ bih, const float* __restrict__ bhh) {
    extern __shared__ float s[];
    float2* WihT2 = (float2*)s;                 // [c(64)][p(96)]
    float2* WhhT2 = WihT2 + 64 * 96;
    float* bihs = (float*)(WhhT2 + 64 * 96);    // 192
    float* bhhs = bihs + 192;                   // 192
    float2* stg = (float2*)(bhhs + 192);        // [warp][NPW][128] dup (m|h)

    int tid = threadIdx.x;
    for (int idx = tid; idx < 64 * 96; idx += GK_THREADS) {
        int c = idx / 96, p = idx % 96;
        WihT2[c * 96 + p] = make_float2(Wih[(2 * p) * HID + c],
                                        Wih[(2 * p + 1) * HID + c]);
        WhhT2[c * 96 + p] = make_float2(Whh[(2 * p) * HID + c],
                                        Whh[(2 * p + 1) * HID + c]);
    }
    for (int idx = tid; idx < 192; idx += GK_THREADS) {
        bihs[idx] = bih[idx];
        bhhs[idx] = bhh[idx];
    }
    __syncthreads();

    int warp = tid >> 5, lane = tid & 31;
    float2* ws = stg + warp * NPW * 128;
    const int ngroups = N_NODES / NPW;  // 12500

    for (int g = blockIdx.x * GK_WARPS + warp; g < ngroups;
         g += gridDim.x * GK_WARPS) {
        int v0 = g * NPW;
#pragma unroll
        for (int n = 0; n < NPW; n++) {
            int v = v0 + n;
            float m0 = g_m[v * HID + lane];
            float m1 = g_m[v * HID + lane + 32];
            float h0 = g_x[v * HID + lane];
            float h1 = g_x[v * HID + lane + 32];
            ws[n * 128 + lane] = make_float2(m0, m0);
            ws[n * 128 + lane + 32] = make_float2(m1, m1);
            ws[n * 128 + 64 + lane] = make_float2(h0, h0);
            ws[n * 128 + 64 + lane + 32] = make_float2(h1, h1);
        }
        __syncwarp();

        unsigned long long ai[NPW][3], ah[NPW][3];
#pragma unroll
        for (int n = 0; n < NPW; n++)
#pragma unroll
            for (int j = 0; j < 3; j++) { ai[n][j] = 0ull; ah[n][j] = 0ull; }

#pragma unroll 2
        for (int c = 0; c < HID; c++) {
            unsigned long long wi0 = ld2u((const float*)(WihT2 + c * 96 + lane));
            unsigned long long wi1 = ld2u((const float*)(WihT2 + c * 96 + lane + 32));
            unsigned long long wi2 = ld2u((const float*)(WihT2 + c * 96 + lane + 64));
            unsigned long long wh0 = ld2u((const float*)(WhhT2 + c * 96 + lane));
            unsigned long long wh1 = ld2u((const float*)(WhhT2 + c * 96 + lane + 32));
            unsigned long long wh2 = ld2u((const float*)(WhhT2 + c * 96 + lane + 64));
#pragma unroll
            for (int n = 0; n < NPW; n++) {
                unsigned long long mv = ld2u((const float*)(ws + n * 128 + c));
                unsigned long long hv = ld2u((const float*)(ws + n * 128 + 64 + c));
                ai[n][0] = fma2(wi0, mv, ai[n][0]);
                ai[n][1] = fma2(wi1, mv, ai[n][1]);
                ai[n][2] = fma2(wi2, mv, ai[n][2]);
                ah[n][0] = fma2(wh0, hv, ah[n][0]);
                ah[n][1] = fma2(wh1, hv, ah[n][1]);
                ah[n][2] = fma2(wh2, hv, ah[n][2]);
            }
        }

        int u0 = 2 * lane;
#pragma unroll
        for (int n = 0; n < NPW; n++) {
            int v = v0 + n;
            float2 ir = unpk(ai[n][0]), hr = unpk(ah[n][0]);
            float2 iz = unpk(ai[n][1]), hz = unpk(ah[n][1]);
            float2 in_ = unpk(ai[n][2]), hn = unpk(ah[n][2]);
            float holdA = ws[n * 128 + 64 + u0].x;
            float holdB = ws[n * 128 + 64 + u0 + 1].x;
            float rA = sigmoidf_(ir.x + bihs[u0] + hr.x + bhhs[u0]);
            float rB = sigmoidf_(ir.y + bihs[u0 + 1] + hr.y + bhhs[u0 + 1]);
            float zA = sigmoidf_(iz.x + bihs[64 + u0] + hz.x + bhhs[64 + u0]);
            float zB = sigmoidf_(iz.y + bihs[64 + u0 + 1] + hz.y + bhhs[64 + u0 + 1]);
            float nA = tanhf(in_.x + bihs[128 + u0] + rA * (hn.x + bhhs[128 + u0]));
            float nB = tanhf(in_.y + bihs[128 + u0 + 1] + rB * (hn.y + bhhs[128 + u0 + 1]));
            float oA = (1.f - zA) * nA + zA * holdA;
            float oB = (1.f - zB) * nB + zB * holdB;
            *(float2*)(g_x + v * HID + u0) = make_float2(oA, oB);
        }
        __syncwarp();
    }
}

// ------------------------------- LSTM cell ---------------------------------
#define LSTM_SMEM_F (256 * 128 + 256 * 64 + 4 * 128 + 4 * 64)

__global__ __launch_bounds__(256, 1)
void lstm_kernel(const float* __restrict__ Wih, const float* __restrict__ Whh,
                 const float* __restrict__ bih, const float* __restrict__ bhh) {
    extern __shared__ float s[];
    float* WihT = s;                   // [c(128)][gate(256)]
    float* WhhT = WihT + 256 * 128;    // [c(64)][gate(256)]
    float* qs_s = WhhT + 256 * 64;     // [4][128]
    float* qh_s = qs_s + 4 * 128;      // [4][64]

    int tid = threadIdx.x;
    for (int idx = tid; idx < 256 * 128; idx += 256) {
        int g = idx >> 7, c = idx & 127;
        WihT[c * 256 + g] = Wih[idx];
    }
    for (int idx = tid; idx < 256 * 64; idx += 256) {
        int g = idx >> 6, c = idx & 63;
        WhhT[c * 256 + g] = Whh[idx];
    }
    int g0 = blockIdx.x * 4;
    for (int idx = tid; idx < 4 * 128; idx += 256)
        qs_s[idx] = g_qstar[g0 * 128 + idx];
    for (int idx = tid; idx < 4 * 64; idx += 256)
        qh_s[idx] = g_qh[g0 * 64 + idx];
    __syncthreads();

    int lg = tid >> 6;
    int u = tid & 63;
    int g = g0 + lg;
    float accI = bih[u] + bhh[u];
    float accF = bih[64 + u] + bhh[64 + u];
    float accG = bih[128 + u] + bhh[128 + u];
    float accO = bih[192 + u] + bhh[192 + u];
    const float* qs = qs_s + lg * 128;
#pragma unroll 4
    for (int c = 0; c < 128; c++) {
        float v = qs[c];
        const float* w = &WihT[c * 256];
        accI += v * w[u];
        accF += v * w[64 + u];
        accG += v * w[128 + u];
        accO += v * w[192 + u];
    }
    const float* qh = qh_s + lg * 64;
#pragma unroll 4
    for (int c = 0; c < 64; c++) {
        float v = qh[c];
        const float* w = &WhhT[c * 256];
        accI += v * w[u];
        accF += v * w[64 + u];
        accG += v * w[128 + u];
        accO += v * w[192 + u];
    }
    float i_ = sigmoidf_(accI), f_ = sigmoidf_(accF);
    float gg = tanhf(accG), o_ = sigmoidf_(accO);
    float c_new = f_ * g_qc[g * 64 + u] + i_ * gg;
    float h_new = o_ * tanhf(c_new);
    g_qc[g * 64 + u] = c_new;
    g_qh[g * 64 + u] = h_new;
}

// ----------------------------- attention steps -----------------------------
__global__ void attn_dot_kernel(const int* __restrict__ batch) {
    int wg = (blockIdx.x * blockDim.x + threadIdx.x) >> 5;
    int lane = threadIdx.x & 31;
    if (wg >= N_NODES) return;
    int v = wg;
    int b = batch[v];
    float p = g_x[v * HID + lane] * g_qh[b * HID + lane] +
              g_x[v * HID + lane + 32] * g_qh[b * HID + lane + 32];
#pragma unroll
    for (int o = 16; o; o >>= 1) p += __shfl_down_sync(0xffffffffu, p, o);
    if (lane == 0) {
        g_e[v] = p;
        atomicMax(&g_emax[b], enc_f(p));
    }
}

__global__ void attn_exp_kernel(const int* __restrict__ batch) {
    int v = blockIdx.x * blockDim.x + threadIdx.x;
    if (v >= N_NODES) return;
    int b = batch[v];
    float a = expf(g_e[v] - dec_f(g_emax[b]));
    g_a[v] = a;
    atomicAdd(&g_asum[b], a);
}

__global__ void attn_rvec_kernel(const int* __restrict__ batch) {
    int wg = (blockIdx.x * blockDim.x + threadIdx.x) >> 5;
    int lane = threadIdx.x & 31;
    if (wg >= N_NODES) return;
    int v = wg;
    int b = batch[v];
    float coef = g_a[v] / g_asum[b];
    atomicAdd(&g_rvec[b * HID + lane], coef * g_x[v * HID + lane]);
    atomicAdd(&g_rvec[b * HID + lane + 32], coef * g_x[v * HID + lane + 32]);
}

__global__ void qstar_kernel() {
    int t = blockIdx.x * blockDim.x + threadIdx.x;
    if (t >= NUM_GRAPHS * HID) return;
    int g = t >> 6, u = t & 63;
    g_qstar[g * 2 * HID + u] = g_qh[t];
    g_qstar[g * 2 * HID + HID + u] = g_rvec[t];
}

// ------------------------------- regressor ---------------------------------
__global__ void reg_kernel(const float* __restrict__ W1,
                           const float* __restrict__ b1,
                           const float* __restrict__ W2,
                           const float* __restrict__ b2,
                           float* __restrict__ out) {
    __shared__ float qs[128];
    __shared__ float red[64];
    int g = blockIdx.x;
    int u = threadIdx.x;  // 64 threads
    qs[u] = g_qstar[g * 128 + u];
    qs[u + 64] = g_qstar[g * 128 + u + 64];
    __syncthreads();
    float acc = b1[u];
#pragma unroll 4
    for (int c = 0; c < 128; c++) acc += qs[c] * W1[c * HID + u];
    red[u] = fmaxf(acc, 0.f) * W2[u];
    __syncthreads();
    for (int sft = 32; sft; sft >>= 1) {
        if (u < sft) red[u] += red[u + sft];
        __syncthreads();
    }
    if (u == 0) out[g] = red[0] + b2[0];
}

// ------------------------------ host driver --------------------------------
extern "C" void kernel_launch(void* const* d_in, const int* in_sizes, int n_in,
                              void* d_out, int out_size) {
    const float* x_feat     = (const float*)d_in[0];
    const int*   edge_index = (const int*)d_in[1];
    const float* edge_attr  = (const float*)d_in[2];
    const int*   batch      = (const int*)d_in[3];
    const float* W_emb = (const float*)d_in[4];
    const float* b_emb = (const float*)d_in[5];
    const float* W_m1  = (const float*)d_in[6];
    const float* b_m1  = (const float*)d_in[7];
    const float* W_m2  = (const float*)d_in[8];
    const float* b_m2  = (const float*)d_in[9];
    const float* gWih  = (const float*)d_in[10];
    const float* gWhh  = (const float*)d_in[11];
    const float* gbih  = (const float*)d_in[12];
    const float* gbhh  = (const float*)d_in[13];
    const float* lWih  = (const float*)d_in[14];
    const float* lWhh  = (const float*)d_in[15];
    const float* lbih  = (const float*)d_in[16];
    const float* lbhh  = (const float*)d_in[17];
    const float* Wr1   = (const float*)d_in[18];
    const float* br1   = (const float*)d_in[19];
    const float* Wr2   = (const float*)d_in[20];
    const float* br2   = (const float*)d_in[21];
    float* out = (float*)d_out;

    const int ek_smem   = EK_SMEM_FLOATS * (int)sizeof(float);
    const int gru_smem  = GRU_SMEM_F * (int)sizeof(float);
    const int lstm_smem = LSTM_SMEM_F * (int)sizeof(float);
    cudaFuncSetAttribute(edge_msg_kernel,
                         cudaFuncAttributeMaxDynamicSharedMemorySize, ek_smem);
    cudaFuncSetAttribute(gru_kernel,
                         cudaFuncAttributeMaxDynamicSharedMemorySize, gru_smem);
    cudaFuncSetAttribute(lstm_kernel,
                         cudaFuncAttributeMaxDynamicSharedMemorySize, lstm_smem);

    // 1. node embedding
    embed_kernel<<<(N_NODES * HID + 255) / 256, 256>>>(x_feat, W_emb, b_emb);

    // 2. message passing rounds
    for (int r = 0; r < NUM_MP; r++) {
        zero_m_kernel<<<(N_NODES * HID + 255) / 256, 256>>>();
        edge_msg_kernel<<<148, EK_THREADS, ek_smem>>>(edge_index, edge_attr,
                                                      W_m1, b_m1, W_m2, b_m2);
        gru_kernel<<<148, GK_THREADS, gru_smem>>>(gWih, gWhh, gbih, gbhh);
    }

    // 3. Set2Set
    zero_s2s_state_kernel<<<(NUM_GRAPHS * 2 * HID + 255) / 256, 256>>>();
    for (int s = 0; s < S2S_STEPS; s++) {
        lstm_kernel<<<NUM_GRAPHS / 4, 256, lstm_smem>>>(lWih, lWhh, lbih, lbhh);
        zero_attn_kernel<<<(NUM_GRAPHS * HID + 255) / 256, 256>>>();
        attn_dot_kernel<<<(N_NODES * 32 + 255) / 256, 256>>>(batch);
        attn_exp_kernel<<<(N_NODES + 255) / 256, 256>>>(batch);
        attn_rvec_kernel<<<(N_NODES * 32 + 255) / 256, 256>>>(batch);
        qstar_kernel<<<(NUM_GRAPHS * HID + 255) / 256, 256>>>();
    }

    // 4. regressor
    reg_kernel<<<NUM_GRAPHS, 64>>>(Wr1, br1, Wr2, br2, out);
    (void)in_sizes; (void)n_in; (void)out_size;
}

// round 11
// speedup vs baseline: 1.2611x; 1.2611x over previous
#include <cuda_runtime.h>

// ---------------------------------------------------------------------------
// MPNN forward, fp32, graph-capturable, allocation-free.
// R11: R2's proven edge-pair FFMA2 structure with EQ=8 (issue-balanced:
// 32 issue slots vs 32 fma-cycles per input channel), float4 staging,
// 14 warps/CTA. GRU = R5 f32x2 version (97us).
// ---------------------------------------------------------------------------

#define N_NODES 50000
#define N_EDGES 800000
#define NODE_DIM 32
#define EDGE_DIM 16
#define HID 64
#define MSG_HID 128
#define NUM_GRAPHS 512
#define NUM_MP 3
#define S2S_STEPS 6
#define IN_DIM (2 * HID + EDGE_DIM)  // 144

// ------------------------- scratch (device globals) ------------------------
__device__ float g_x[N_NODES * HID];
__device__ float g_m[N_NODES * HID];
__device__ float g_qh[NUM_GRAPHS * HID];
__device__ float g_qc[NUM_GRAPHS * HID];
__device__ float g_qstar[NUM_GRAPHS * 2 * HID];
__device__ float g_e[N_NODES];
__device__ float g_a[N_NODES];
__device__ unsigned g_emax[NUM_GRAPHS];
__device__ float g_asum[NUM_GRAPHS];
__device__ float g_rvec[NUM_GRAPHS * HID];

__device__ __forceinline__ float sigmoidf_(float x) { return 1.f / (1.f + expf(-x)); }

__device__ __forceinline__ unsigned enc_f(float f) {
    unsigned u = __float_as_uint(f);
    return (u & 0x80000000u) ? ~u : (u | 0x80000000u);
}
__device__ __forceinline__ float dec_f(unsigned k) {
    return (k & 0x80000000u) ? __uint_as_float(k & 0x7fffffffu)
                             : __uint_as_float(~k);
}

// ----------------------- packed f32x2 helpers (sm_100+) --------------------
__device__ __forceinline__ unsigned long long fma2(unsigned long long a,
                                                   unsigned long long b,
                                                   unsigned long long c) {
    unsigned long long d;
    asm("fma.rn.f32x2 %0, %1, %2, %3;" : "=l"(d) : "l"(a), "l"(b), "l"(c));
    return d;
}
__device__ __forceinline__ unsigned long long dup2(float x) {
    unsigned long long d;
    asm("mov.b64 %0, {%1, %1};" : "=l"(d) : "f"(x));
    return d;
}
__device__ __forceinline__ float2 unpk(unsigned long long v) {
    float lo, hi;
    asm("mov.b64 {%0, %1}, %2;" : "=f"(lo), "=f"(hi) : "l"(v));
    return make_float2(lo, hi);
}
__device__ __forceinline__ unsigned long long ld2u(const float* p) {
    return *(const unsigned long long*)p;
}

// ------------------------------ zero kernels -------------------------------
__global__ void zero_m_kernel() {
    int t = blockIdx.x * blockDim.x + threadIdx.x;
    if (t < N_NODES * HID) g_m[t] = 0.f;
}
__global__ void zero_s2s_state_kernel() {
    int t = blockIdx.x * blockDim.x + threadIdx.x;
    if (t < NUM_GRAPHS * HID) { g_qh[t] = 0.f; g_qc[t] = 0.f; }
    if (t < NUM_GRAPHS * 2 * HID) g_qstar[t] = 0.f;
}
__global__ void zero_attn_kernel() {
    int t = blockIdx.x * blockDim.x + threadIdx.x;
    if (t < NUM_GRAPHS) { g_emax[t] = 0u; g_asum[t] = 0.f; }
    if (t < NUM_GRAPHS * HID) g_rvec[t] = 0.f;
}

// ------------------------------- embedding ---------------------------------
__global__ void embed_kernel(const float* __restrict__ xf,
                             const float* __restrict__ W,
                             const float* __restrict__ b) {
    int t = blockIdx.x * blockDim.x + threadIdx.x;
    if (t >= N_NODES * HID) return;
    int v = t >> 6, o = t & 63;
    const float* xr = xf + v * NODE_DIM;
    float acc = b[o];
#pragma unroll
    for (int c = 0; c < NODE_DIM; c++) acc += xr[c] * W[c * HID + o];
    g_x[t] = acc;
}

// ------------------------- edge message MLP kernel -------------------------
// 14 warps, EQ=8 edges/warp. Staging channel-major, stride 8 floats:
//   win[idx*8 + k] = feature idx of edge k (pairs (2p,2p+1) adjacent ->
//   one LDS.64 yields an edge-pair f32x2 operand, exactly R2's scheme).
#define EK_THREADS 448
#define EK_WARPS 14
#define EQ 8
#define WIN_F (IN_DIM * EQ)    // 1152
#define WHID_F (MSG_HID * EQ)  // 1024
#define EK_SMEM_FLOATS (IN_DIM * MSG_HID + MSG_HID + MSG_HID * HID + HID + \
                        EK_WARPS * (WIN_F + WHID_F))

__global__ __launch_bounds__(EK_THREADS, 1)
void edge_msg_kernel(const int* __restrict__ ei, const float* __restrict__ ea,
                     const float* __restrict__ W1, const float* __restrict__ b1,
                     const float* __restrict__ W2, const float* __restrict__ b2) {
    extern __shared__ float smem[];
    float* W1s  = smem;                              // 144*128 row-major
    float* b1s  = W1s + IN_DIM * MSG_HID;            // 128
    float* W2s  = b1s + MSG_HID;                     // 128*64 row-major
    float* b2s  = W2s + MSG_HID * HID;               // 64
    float* win_all  = b2s + HID;                     // warps * 1152
    float* whid_all = win_all + EK_WARPS * WIN_F;    // warps * 1024

    int tid = threadIdx.x;
    for (int i = tid; i < IN_DIM * MSG_HID / 4; i += EK_THREADS)
        ((float4*)W1s)[i] = ((const float4*)W1)[i];
    for (int i = tid; i < MSG_HID; i += EK_THREADS) b1s[i] = b1[i];
    for (int i = tid; i < MSG_HID * HID / 4; i += EK_THREADS)
        ((float4*)W2s)[i] = ((const float4*)W2)[i];
    for (int i = tid; i < HID; i += EK_THREADS) b2s[i] = b2[i];
    __syncthreads();

    int warp = tid >> 5, lane = tid & 31;
    float* win  = win_all + warp * WIN_F;
    float* whid = whid_all + warp * WHID_F;
    const int* src = ei;
    const int* dst = ei + N_EDGES;

    const int noct = N_EDGES / EQ;  // 100000
    for (int q = blockIdx.x * EK_WARPS + warp; q < noct;
         q += gridDim.x * EK_WARPS) {
        int e0 = q * EQ;
        int d[EQ], s_[EQ];
#pragma unroll
        for (int k = 0; k < EQ; k++) {
            s_[k] = __ldg(src + e0 + k);
            d[k]  = __ldg(dst + e0 + k);
        }
        // stage channel-major: win[idx*8 + k]
#pragma unroll
        for (int j = 0; j < 5; j++) {
            int idx = lane + 32 * j;
            if (idx < IN_DIM) {
                float v[EQ];
#pragma unroll
                for (int k = 0; k < EQ; k++) {
                    if (j < 2) v[k] = g_x[d[k] * HID + idx];
                    else if (j < 4) v[k] = g_x[s_[k] * HID + (idx - HID)];
                    else v[k] = __ldg(ea + (e0 + k) * EDGE_DIM + (idx - 2 * HID));
                }
                float* base = win + idx * EQ;
                *(float4*)base = make_float4(v[0], v[1], v[2], v[3]);
                *(float4*)(base + 4) = make_float4(v[4], v[5], v[6], v[7]);
            }
        }
        __syncwarp();

        // ---- layer 1: lane computes channels {lane,+32,+64,+96} for 8
        // edges packed as 4 edge-pairs. 32 issue slots vs 32 fma-cycles/i.
        unsigned long long acc[4][4];  // [out j][pair p]
#pragma unroll
        for (int j = 0; j < 4; j++)
#pragma unroll
            for (int p = 0; p < 4; p++) acc[j][p] = 0ull;

#pragma unroll 2
        for (int i = 0; i < IN_DIM; i++) {
            const float* wr = W1s + i * MSG_HID + lane;
            unsigned long long w0 = dup2(wr[0]);
            unsigned long long w1 = dup2(wr[32]);
            unsigned long long w2 = dup2(wr[64]);
            unsigned long long w3 = dup2(wr[96]);
            const float* base = win + i * EQ;
            unsigned long long in0 = ld2u(base);
            unsigned long long in1 = ld2u(base + 2);
            unsigned long long in2 = ld2u(base + 4);
            unsigned long long in3 = ld2u(base + 6);
            acc[0][0] = fma2(w0, in0, acc[0][0]);
            acc[0][1] = fma2(w0, in1, acc[0][1]);
            acc[0][2] = fma2(w0, in2, acc[0][2]);
            acc[0][3] = fma2(w0, in3, acc[0][3]);
            acc[1][0] = fma2(w1, in0, acc[1][0]);
            acc[1][1] = fma2(w1, in1, acc[1][1]);
            acc[1][2] = fma2(w1, in2, acc[1][2]);
            acc[1][3] = fma2(w1, in3, acc[1][3]);
            acc[2][0] = fma2(w2, in0, acc[2][0]);
            acc[2][1] = fma2(w2, in1, acc[2][1]);
            acc[2][2] = fma2(w2, in2, acc[2][2]);
            acc[2][3] = fma2(w2, in3, acc[2][3]);
            acc[3][0] = fma2(w3, in0, acc[3][0]);
            acc[3][1] = fma2(w3, in1, acc[3][1]);
            acc[3][2] = fma2(w3, in2, acc[3][2]);
            acc[3][3] = fma2(w3, in3, acc[3][3]);
        }
        // bias + relu; store channel-major stride 8
#pragma unroll
        for (int j = 0; j < 4; j++) {
            int ch = lane + 32 * j;
            float b = b1s[ch];
            float2 f0 = unpk(acc[j][0]);
            float2 f1 = unpk(acc[j][1]);
            float2 f2 = unpk(acc[j][2]);
            float2 f3 = unpk(acc[j][3]);
            float* hb = whid + ch * EQ;
            *(float4*)hb = make_float4(fmaxf(f0.x + b, 0.f), fmaxf(f0.y + b, 0.f),
                                       fmaxf(f1.x + b, 0.f), fmaxf(f1.y + b, 0.f));
            *(float4*)(hb + 4) = make_float4(fmaxf(f2.x + b, 0.f), fmaxf(f2.y + b, 0.f),
                                             fmaxf(f3.x + b, 0.f), fmaxf(f3.y + b, 0.f));
        }
        __syncwarp();

        // ---- layer 2: lane computes channels {lane, lane+32} ----
        unsigned long long acc2[2][4];
#pragma unroll
        for (int j = 0; j < 2; j++)
#pragma unroll
            for (int p = 0; p < 4; p++) acc2[j][p] = 0ull;
#pragma unroll 2
        for (int i = 0; i < MSG_HID; i++) {
            const float* wr = W2s + i * HID + lane;
            unsigned long long w0 = dup2(wr[0]);
            unsigned long long w1 = dup2(wr[32]);
            const float* base = whid + i * EQ;
            unsigned long long h0 = ld2u(base);
            unsigned long long h1 = ld2u(base + 2);
            unsigned long long h2 = ld2u(base + 4);
            unsigned long long h3 = ld2u(base + 6);
            acc2[0][0] = fma2(w0, h0, acc2[0][0]);
            acc2[0][1] = fma2(w0, h1, acc2[0][1]);
            acc2[0][2] = fma2(w0, h2, acc2[0][2]);
            acc2[0][3] = fma2(w0, h3, acc2[0][3]);
            acc2[1][0] = fma2(w1, h0, acc2[1][0]);
            acc2[1][1] = fma2(w1, h1, acc2[1][1]);
            acc2[1][2] = fma2(w1, h2, acc2[1][2]);
            acc2[1][3] = fma2(w1, h3, acc2[1][3]);
        }
#pragma unroll
        for (int j = 0; j < 2; j++) {
            int ch = lane + 32 * j;
            float b = b2s[ch];
#pragma unroll
            for (int p = 0; p < 4; p++) {
                float2 f = unpk(acc2[j][p]);
                atomicAdd(&g_m[d[2 * p] * HID + ch], f.x + b);
                atomicAdd(&g_m[d[2 * p + 1] * HID + ch], f.y + b);
            }
        }
        __syncwarp();
    }
}

// --------------------------------- GRU -------------------------------------
#define GK_THREADS 256
#define GK_WARPS 8
#define NPW 4
#define GRU_SMEM_F (64 * 96 * 2 * 2 + 384 + GK_WARPS * NPW * 128 * 2)

__global__ __launch_bounds__(GK_THREADS, 1)
void gru_kernel(const float* __restrict__ Wih, const float* __restrict__ Whh,
                const float* __restrict__ bih, const float* __restrict__ bhh) {
    extern __shared__ float s[];
    float2* WihT2 = (float2*)s;                 // [c(64)][p(96)]
    float2* WhhT2 = WihT2 + 64 * 96;
    float* bihs = (float*)(WhhT2 + 64 * 96);    // 192
    float* bhhs = bihs + 192;                   // 192
    float2* stg = (float2*)(bhhs + 192);        // [warp][NPW][128] dup (m|h)

    int tid = threadIdx.x;
    for (int idx = tid; idx < 64 * 96; idx += GK_THREADS) {
        int c = idx / 96, p = idx % 96;
        WihT2[c * 96 + p] = make_float2(Wih[(2 * p) * HID + c],
                                        Wih[(2 * p + 1) * HID + c]);
        WhhT2[c * 96 + p] = make_float2(Whh[(2 * p) * HID + c],
                                        Whh[(2 * p + 1) * HID + c]);
    }
    for (int idx = tid; idx < 192; idx += GK_THREADS) {
        bihs[idx] = bih[idx];
        bhhs[idx] = bhh[idx];
    }
    __syncthreads();

    int warp = tid >> 5, lane = tid & 31;
    float2* ws = stg + warp * NPW * 128;
    const int ngroups = N_NODES / NPW;  // 12500

    for (int g = blockIdx.x * GK_WARPS + warp; g < ngroups;
         g += gridDim.x * GK_WARPS) {
        int v0 = g * NPW;
#pragma unroll
        for (int n = 0; n < NPW; n++) {
            int v = v0 + n;
            float m0 = g_m[v * HID + lane];
            float m1 = g_m[v * HID + lane + 32];
            float h0 = g_x[v * HID + lane];
            float h1 = g_x[v * HID + lane + 32];
            ws[n * 128 + lane] = make_float2(m0, m0);
            ws[n * 128 + lane + 32] = make_float2(m1, m1);
            ws[n * 128 + 64 + lane] = make_float2(h0, h0);
            ws[n * 128 + 64 + lane + 32] = make_float2(h1, h1);
        }
        __syncwarp();

        unsigned long long ai[NPW][3], ah[NPW][3];
#pragma unroll
        for (int n = 0; n < NPW; n++)
#pragma unroll
            for (int j = 0; j < 3; j++) { ai[n][j] = 0ull; ah[n][j] = 0ull; }

#pragma unroll 2
        for (int c = 0; c < HID; c++) {
            unsigned long long wi0 = ld2u((const float*)(WihT2 + c * 96 + lane));
            unsigned long long wi1 = ld2u((const float*)(WihT2 + c * 96 + lane + 32));
            unsigned long long wi2 = ld2u((const float*)(WihT2 + c * 96 + lane + 64));
            unsigned long long wh0 = ld2u((const float*)(WhhT2 + c * 96 + lane));
            unsigned long long wh1 = ld2u((const float*)(WhhT2 + c * 96 + lane + 32));
            unsigned long long wh2 = ld2u((const float*)(WhhT2 + c * 96 + lane + 64));
#pragma unroll
            for (int n = 0; n < NPW; n++) {
                unsigned long long mv = ld2u((const float*)(ws + n * 128 + c));
                unsigned long long hv = ld2u((const float*)(ws + n * 128 + 64 + c));
                ai[n][0] = fma2(wi0, mv, ai[n][0]);
                ai[n][1] = fma2(wi1, mv, ai[n][1]);
                ai[n][2] = fma2(wi2, mv, ai[n][2]);
                ah[n][0] = fma2(wh0, hv, ah[n][0]);
                ah[n][1] = fma2(wh1, hv, ah[n][1]);
                ah[n][2] = fma2(wh2, hv, ah[n][2]);
            }
        }

        int u0 = 2 * lane;
#pragma unroll
        for (int n = 0; n < NPW; n++) {
            int v = v0 + n;
            float2 ir = unpk(ai[n][0]), hr = unpk(ah[n][0]);
            float2 iz = unpk(ai[n][1]), hz = unpk(ah[n][1]);
            float2 in_ = unpk(ai[n][2]), hn = unpk(ah[n][2]);
            float holdA = ws[n * 128 + 64 + u0].x;
            float holdB = ws[n * 128 + 64 + u0 + 1].x;
            float rA = sigmoidf_(ir.x + bihs[u0] + hr.x + bhhs[u0]);
            float rB = sigmoidf_(ir.y + bihs[u0 + 1] + hr.y + bhhs[u0 + 1]);
            float zA = sigmoidf_(iz.x + bihs[64 + u0] + hz.x + bhhs[64 + u0]);
            float zB = sigmoidf_(iz.y + bihs[64 + u0 + 1] + hz.y + bhhs[64 + u0 + 1]);
            float nA = tanhf(in_.x + bihs[128 + u0] + rA * (hn.x + bhhs[128 + u0]));
            float nB = tanhf(in_.y + bihs[128 + u0 + 1] + rB * (hn.y + bhhs[128 + u0 + 1]));
            float oA = (1.f - zA) * nA + zA * holdA;
            float oB = (1.f - zB) * nB + zB * holdB;
            *(float2*)(g_x + v * HID + u0) = make_float2(oA, oB);
        }
        __syncwarp();
    }
}

// ------------------------------- LSTM cell ---------------------------------
#define LSTM_SMEM_F (256 * 128 + 256 * 64 + 4 * 128 + 4 * 64)

__global__ __launch_bounds__(256, 1)
void lstm_kernel(const float* __restrict__ Wih, const float* __restrict__ Whh,
                 const float* __restrict__ bih, const float* __restrict__ bhh) {
    extern __shared__ float s[];
    float* WihT = s;                   // [c(128)][gate(256)]
    float* WhhT = WihT + 256 * 128;    // [c(64)][gate(256)]
    float* qs_s = WhhT + 256 * 64;     // [4][128]
    float* qh_s = qs_s + 4 * 128;      // [4][64]

    int tid = threadIdx.x;
    for (int idx = tid; idx < 256 * 128; idx += 256) {
        int g = idx >> 7, c = idx & 127;
        WihT[c * 256 + g] = Wih[idx];
    }
    for (int idx = tid; idx < 256 * 64; idx += 256) {
        int g = idx >> 6, c = idx & 63;
        WhhT[c * 256 + g] = Whh[idx];
    }
    int g0 = blockIdx.x * 4;
    for (int idx = tid; idx < 4 * 128; idx += 256)
        qs_s[idx] = g_qstar[g0 * 128 + idx];
    for (int idx = tid; idx < 4 * 64; idx += 256)
        qh_s[idx] = g_qh[g0 * 64 + idx];
    __syncthreads();

    int lg = tid >> 6;
    int u = tid & 63;
    int g = g0 + lg;
    float accI = bih[u] + bhh[u];
    float accF = bih[64 + u] + bhh[64 + u];
    float accG = bih[128 + u] + bhh[128 + u];
    float accO = bih[192 + u] + bhh[192 + u];
    const float* qs = qs_s + lg * 128;
#pragma unroll 4
    for (int c = 0; c < 128; c++) {
        float v = qs[c];
        const float* w = &WihT[c * 256];
        accI += v * w[u];
        accF += v * w[64 + u];
        accG += v * w[128 + u];
        accO += v * w[192 + u];
    }
    const float* qh = qh_s + lg * 64;
#pragma unroll 4
    for (int c = 0; c < 64; c++) {
        float v = qh[c];
        const float* w = &WhhT[c * 256];
        accI += v * w[u];
        accF += v * w[64 + u];
        accG += v * w[128 + u];
        accO += v * w[192 + u];
    }
    float i_ = sigmoidf_(accI), f_ = sigmoidf_(accF);
    float gg = tanhf(accG), o_ = sigmoidf_(accO);
    float c_new = f_ * g_qc[g * 64 + u] + i_ * gg;
    float h_new = o_ * tanhf(c_new);
    g_qc[g * 64 + u] = c_new;
    g_qh[g * 64 + u] = h_new;
}

// ----------------------------- attention steps -----------------------------
__global__ void attn_dot_kernel(const int* __restrict__ batch) {
    int wg = (blockIdx.x * blockDim.x + threadIdx.x) >> 5;
    int lane = threadIdx.x & 31;
    if (wg >= N_NODES) return;
    int v = wg;
    int b = batch[v];
    float p = g_x[v * HID + lane] * g_qh[b * HID + lane] +
              g_x[v * HID + lane + 32] * g_qh[b * HID + lane + 32];
#pragma unroll
    for (int o = 16; o; o >>= 1) p += __shfl_down_sync(0xffffffffu, p, o);
    if (lane == 0) {
        g_e[v] = p;
        atomicMax(&g_emax[b], enc_f(p));
    }
}

__global__ void attn_exp_kernel(const int* __restrict__ batch) {
    int v = blockIdx.x * blockDim.x + threadIdx.x;
    if (v >= N_NODES) return;
    int b = batch[v];
    float a = expf(g_e[v] - dec_f(g_emax[b]));
    g_a[v] = a;
    atomicAdd(&g_asum[b], a);
}

__global__ void attn_rvec_kernel(const int* __restrict__ batch) {
    int wg = (blockIdx.x * blockDim.x + threadIdx.x) >> 5;
    int lane = threadIdx.x & 31;
    if (wg >= N_NODES) return;
    int v = wg;
    int b = batch[v];
    float coef = g_a[v] / g_asum[b];
    atomicAdd(&g_rvec[b * HID + lane], coef * g_x[v * HID + lane]);
    atomicAdd(&g_rvec[b * HID + lane + 32], coef * g_x[v * HID + lane + 32]);
}

__global__ void qstar_kernel() {
    int t = blockIdx.x * blockDim.x + threadIdx.x;
    if (t >= NUM_GRAPHS * HID) return;
    int g = t >> 6, u = t & 63;
    g_qstar[g * 2 * HID + u] = g_qh[t];
    g_qstar[g * 2 * HID + HID + u] = g_rvec[t];
}

// ------------------------------- regressor ---------------------------------
__global__ void reg_kernel(const float* __restrict__ W1,
                           const float* __restrict__ b1,
                           const float* __restrict__ W2,
                           const float* __restrict__ b2,
                           float* __restrict__ out) {
    __shared__ float qs[128];
    __shared__ float red[64];
    int g = blockIdx.x;
    int u = threadIdx.x;  // 64 threads
    qs[u] = g_qstar[g * 128 + u];
    qs[u + 64] = g_qstar[g * 128 + u + 64];
    __syncthreads();
    float acc = b1[u];
#pragma unroll 4
    for (int c = 0; c < 128; c++) acc += qs[c] * W1[c * HID + u];
    red[u] = fmaxf(acc, 0.f) * W2[u];
    __syncthreads();
    for (int sft = 32; sft; sft >>= 1) {
        if (u < sft) red[u] += red[u + sft];
        __syncthreads();
    }
    if (u == 0) out[g] = red[0] + b2[0];
}

// ------------------------------ host driver --------------------------------
extern "C" void kernel_launch(void* const* d_in, const int* in_sizes, int n_in,
                              void* d_out, int out_size) {
    const float* x_feat     = (const float*)d_in[0];
    const int*   edge_index = (const int*)d_in[1];
    const float* edge_attr  = (const float*)d_in[2];
    const int*   batch      = (const int*)d_in[3];
    const float* W_emb = (const float*)d_in[4];
    const float* b_emb = (const float*)d_in[5];
    const float* W_m1  = (const float*)d_in[6];
    const float* b_m1  = (const float*)d_in[7];
    const float* W_m2  = (const float*)d_in[8];
    const float* b_m2  = (const float*)d_in[9];
    const float* gWih  = (const float*)d_in[10];
    const float* gWhh  = (const float*)d_in[11];
    const float* gbih  = (const float*)d_in[12];
    const float* gbhh  = (const float*)d_in[13];
    const float* lWih  = (const float*)d_in[14];
    const float* lWhh  = (const float*)d_in[15];
    const float* lbih  = (const float*)d_in[16];
    const float* lbhh  = (const float*)d_in[17];
    const float* Wr1   = (const float*)d_in[18];
    const float* br1   = (const float*)d_in[19];
    const float* Wr2   = (const float*)d_in[20];
    const float* br2   = (const float*)d_in[21];
    float* out = (float*)d_out;

    const int ek_smem   = EK_SMEM_FLOATS * (int)sizeof(float);
    const int gru_smem  = GRU_SMEM_F * (int)sizeof(float);
    const int lstm_smem = LSTM_SMEM_F * (int)sizeof(float);
    cudaFuncSetAttribute(edge_msg_kernel,
                         cudaFuncAttributeMaxDynamicSharedMemorySize, ek_smem);
    cudaFuncSetAttribute(gru_kernel,
                         cudaFuncAttributeMaxDynamicSharedMemorySize, gru_smem);
    cudaFuncSetAttribute(lstm_kernel,
                         cudaFuncAttributeMaxDynamicSharedMemorySize, lstm_smem);

    // 1. node embedding
    embed_kernel<<<(N_NODES * HID + 255) / 256, 256>>>(x_feat, W_emb, b_emb);

    // 2. message passing rounds
    for (int r = 0; r < NUM_MP; r++) {
        zero_m_kernel<<<(N_NODES * HID + 255) / 256, 256>>>();
        edge_msg_kernel<<<148, EK_THREADS, ek_smem>>>(edge_index, edge_attr,
                                                      W_m1, b_m1, W_m2, b_m2);
        gru_kernel<<<148, GK_THREADS, gru_smem>>>(gWih, gWhh, gbih, gbhh);
    }

    // 3. Set2Set
    zero_s2s_state_kernel<<<(NUM_GRAPHS * 2 * HID + 255) / 256, 256>>>();
    for (int s = 0; s < S2S_STEPS; s++) {
        lstm_kernel<<<NUM_GRAPHS / 4, 256, lstm_smem>>>(lWih, lWhh, lbih, lbhh);
        zero_attn_kernel<<<(NUM_GRAPHS * HID + 255) / 256, 256>>>();
        attn_dot_kernel<<<(N_NODES * 32 + 255) / 256, 256>>>(batch);
        attn_exp_kernel<<<(N_NODES + 255) / 256, 256>>>(batch);
        attn_rvec_kernel<<<(N_NODES * 32 + 255) / 256, 256>>>(batch);
        qstar_kernel<<<(NUM_GRAPHS * HID + 255) / 256, 256>>>();
    }

    // 4. regressor
    reg_kernel<<<NUM_GRAPHS, 64>>>(Wr1, br1, Wr2, br2, out);
    (void)in_sizes; (void)n_in; (void)out_size;
}